// round 8
// baseline (speedup 1.0000x reference)
#include <cuda_runtime.h>
#include <stdint.h>
#include <math.h>

// ---------------------------------------------------------------------------
// JAX threefry2x32 (key = (0,1) from jax.random.key(1)), partitionable mode:
// bits[j] = out0 ^ out1 of threefry2x32((0,1), (hi=0, lo=j))
// (verified exact in R4: rel_err 5.3e-8)
// ---------------------------------------------------------------------------
__device__ __forceinline__ uint32_t rotl32(uint32_t x, int r) {
    return (x << r) | (x >> (32 - r));
}

__device__ __forceinline__ uint32_t jax_bits(uint32_t j) {
    uint32_t x0 = 0u, x1 = j;
    const uint32_t ks0 = 0u, ks1 = 1u, ks2 = 0x1BD11BDBu;
    x0 += ks0; x1 += ks1;
#define TF_R(r) { x0 += x1; x1 = rotl32(x1, (r)); x1 ^= x0; }
    TF_R(13) TF_R(15) TF_R(26) TF_R(6)
    x0 += ks1; x1 += ks2 + 1u;
    TF_R(17) TF_R(29) TF_R(16) TF_R(24)
    x0 += ks2; x1 += ks0 + 2u;
    TF_R(13) TF_R(15) TF_R(26) TF_R(6)
    x0 += ks0; x1 += ks1 + 3u;
    TF_R(17) TF_R(29) TF_R(16) TF_R(24)
    x0 += ks1; x1 += ks2 + 4u;
    TF_R(13) TF_R(15) TF_R(26) TF_R(6)
    x0 += ks2; x1 += ks0 + 5u;
#undef TF_R
    return x0 ^ x1;
}

__device__ __forceinline__ float jax_gumbel(uint32_t j) {
    uint32_t bits = jax_bits(j);
    float f = __uint_as_float((bits >> 9) | 0x3f800000u) - 1.0f;
    const float TINY = 1.1754943508222875e-38f;
    float u = fmaxf(TINY, f + TINY);
    return -logf(-logf(u));
}

__device__ __forceinline__ void lin_coef(int v, int& a, int& b, float& wa, float& wb) {
    int j = v >> 1;
    if ((v & 1) == 0) { a = j - 1; b = j;     wa = 0.25f; wb = 0.75f; }
    else              { a = j;     b = j + 1; wa = 0.75f; wb = 0.25f; }
    a = max(0, min(3, a));
    b = max(0, min(3, b));
}

// ---------------------------------------------------------------------------
// Gate computation: msh[64] (channel max, in smem) -> gate[64] (smem).
// Entered with all 512 threads; contains internal barriers.
// ---------------------------------------------------------------------------
__device__ void compute_gate(int b, int t,
                             const float* __restrict__ msh,
                             float* c0, float* c1, float* up, float* hsh,
                             float* gate, const float* __restrict__ ws)
{
    // 2a: 2x2 windows + probabilistic pool
    if (t < 16) {
        int wy = t >> 2, wx = t & 3;
        float win0 = msh[(2 * wy) * 8 + 2 * wx];
        float win1 = msh[(2 * wy) * 8 + 2 * wx + 1];
        float win2 = msh[(2 * wy + 1) * 8 + 2 * wx];
        float win3 = msh[(2 * wy + 1) * 8 + 2 * wx + 1];
        float winc[4];
        float winv[4] = {win0, win1, win2, win3};
#pragma unroll
        for (int k = 0; k < 4; ++k) {
            float v = winv[k];
            winc[k] = (isnan(v) || isinf(v) || v < 0.0f) ? 1e-8f : v;
        }
        uint32_t base = (uint32_t)(b * 64 + t * 4);
        float best = -INFINITY; int arg = 0;
#pragma unroll
        for (int k = 0; k < 4; ++k) {
            float val = winc[k] + jax_gumbel(base + (uint32_t)k);
            if (val > best) { best = val; arg = k; }
        }
        float mo2 = winc[arg];
        float mo3 = fmaxf(fmaxf(win0, win1), fmaxf(win2, win3));
        float ao4 = (win0 + win1 + win2 + win3) * 0.25f;
        c0[t] = 0.1f * mo2 + 0.6f * mo3 + 0.3f * ao4;
    }
    __syncthreads();

    // 2b: 3x3 conv (bias-free) on 4x4, zero pad
    if (t < 16) {
        int y = t >> 2, xx = t & 3;
        float acc = 0.0f;
#pragma unroll
        for (int dy = 0; dy < 3; ++dy)
#pragma unroll
            for (int dx = 0; dx < 3; ++dx) {
                int yy = y + dy - 1, xc = xx + dx - 1;
                if (yy >= 0 && yy < 4 && xc >= 0 && xc < 4)
                    acc += c0[yy * 4 + xc] * ws[dy * 3 + dx];
            }
        c1[t] = acc;
    }
    __syncthreads();

    // 2c: bilinear upsample 4->8
    if (t < 64) {
        int y = t >> 3, xx = t & 7;
        int ya, yb2, xa, xb2; float wya, wyb, wxa, wxb;
        lin_coef(y, ya, yb2, wya, wyb);
        lin_coef(xx, xa, xb2, wxa, wxb);
        up[t] = wya * (wxa * c1[ya * 4 + xa] + wxb * c1[ya * 4 + xb2]) +
                wyb * (wxa * c1[yb2 * 4 + xa] + wxb * c1[yb2 * 4 + xb2]);
    }
    __syncthreads();

    // 2d: conv5 (2->4 ch, 3x3) + relu
    if (t < 256) {
        int o = t >> 6, p = t & 63, y = p >> 3, xx = p & 7;
        float acc = ws[81 + o];
#pragma unroll
        for (int dy = 0; dy < 3; ++dy)
#pragma unroll
            for (int dx = 0; dx < 3; ++dx) {
                int yy = y + dy - 1, xc = xx + dx - 1;
                if (yy >= 0 && yy < 8 && xc >= 0 && xc < 8) {
                    int pp = yy * 8 + xc;
                    acc += msh[pp] * ws[9 + ((o * 2 + 0) * 3 + dy) * 3 + dx];
                    acc += up[pp]  * ws[9 + ((o * 2 + 1) * 3 + dy) * 3 + dx];
                }
            }
        hsh[o * 64 + p] = fmaxf(acc, 0.0f);
    }
    __syncthreads();

    // 2e: conv6 (4->1 ch, 3x3) + sigmoid
    if (t < 64) {
        int y = t >> 3, xx = t & 7;
        float acc = ws[121];
#pragma unroll
        for (int o = 0; o < 4; ++o)
#pragma unroll
            for (int dy = 0; dy < 3; ++dy)
#pragma unroll
                for (int dx = 0; dx < 3; ++dx) {
                    int yy = y + dy - 1, xc = xx + dx - 1;
                    if (yy >= 0 && yy < 8 && xc >= 0 && xc < 8)
                        acc += hsh[o * 64 + yy * 8 + xc] * ws[85 + (o * 3 + dy) * 3 + dx];
                }
        gate[t] = 1.0f / (1.0f + expf(-acc));
    }
    __syncthreads();
}

// ---------------------------------------------------------------------------
// Pipelined kernel: grid = 256, CTA i owns batches i and i+256.
//   step1: read x[b0] -> max0                       (DRAM read)
//   step2: gate0 (tiny, then gate -> regs)
//   step3: FUSED  write out[b0] + read x[b1] -> max1 (DRAM read+write overlap)
//   step4: gate1
//   step5: read x[b1] (L2) + write out[b1]          (DRAM write)
// ---------------------------------------------------------------------------
__global__ void __launch_bounds__(512)
sa_layer_kernel(const float* __restrict__ x,
                const float* __restrict__ w1,
                const float* __restrict__ w5,
                const float* __restrict__ b5,
                const float* __restrict__ w6,
                const float* __restrict__ b6,
                float* __restrict__ out)
{
    __shared__ float red[2048];
    __shared__ float msh[64];
    __shared__ float c0[16], c1[16], up[64];
    __shared__ float hsh[256];
    __shared__ float gate[64];
    __shared__ float ws[122];

    const int t = threadIdx.x;
    const int b0 = blockIdx.x;
    const int b1 = blockIdx.x + 256;

    const float4* xb0 = (const float4*)(x + (size_t)b0 * 65536);
    const float4* xb1 = (const float4*)(x + (size_t)b1 * 65536);
    float4* ob0 = (float4*)(out + (size_t)b0 * 65536);
    float4* ob1 = (float4*)(out + (size_t)b1 * 65536);

    if (t < 9)        ws[t] = w1[t];
    else if (t < 81)  ws[t] = w5[t - 9];
    else if (t < 85)  ws[t] = b5[t - 81];
    else if (t < 121) ws[t] = w6[t - 85];
    else if (t == 121) ws[121] = b6[0];

    // ---- step 1: channel max of batch b0 (pure DRAM read, fills L2) ---------
    float4 vmax = make_float4(-INFINITY, -INFINITY, -INFINITY, -INFINITY);
#pragma unroll 8
    for (int it = 0; it < 32; ++it) {
        float4 v = __ldg(&xb0[it * 512 + t]);
        vmax.x = fmaxf(vmax.x, v.x);
        vmax.y = fmaxf(vmax.y, v.y);
        vmax.z = fmaxf(vmax.z, v.z);
        vmax.w = fmaxf(vmax.w, v.w);
    }
    ((float4*)red)[t] = vmax;
    __syncthreads();
    if (t < 64) {
        float mv = -INFINITY;
#pragma unroll 8
        for (int i = 0; i < 32; ++i) mv = fmaxf(mv, red[t + 64 * i]);
        msh[t] = mv;
    }
    __syncthreads();

    // ---- step 2: gate for b0 -------------------------------------------------
    compute_gate(b0, t, msh, c0, c1, up, hsh, gate, ws);
    const int p0 = (t & 15) * 4;
    float4 g0 = make_float4(gate[p0], gate[p0 + 1], gate[p0 + 2], gate[p0 + 3]);
    __syncthreads();   // everyone has g0 in regs before smem reuse

    // ---- step 3: FUSED out[b0] = relu(x[b0]*g0)  +  max over x[b1] ----------
    vmax = make_float4(-INFINITY, -INFINITY, -INFINITY, -INFINITY);
#pragma unroll 4
    for (int it = 0; it < 32; ++it) {
        float4 v1 = __ldg(&xb1[it * 512 + t]);      // DRAM read, keep in L2
        float4 v0 = __ldcs(&xb0[it * 512 + t]);     // L2 hit, evict-first
        vmax.x = fmaxf(vmax.x, v1.x);
        vmax.y = fmaxf(vmax.y, v1.y);
        vmax.z = fmaxf(vmax.z, v1.z);
        vmax.w = fmaxf(vmax.w, v1.w);
        v0.x = fmaxf(v0.x * g0.x, 0.0f);
        v0.y = fmaxf(v0.y * g0.y, 0.0f);
        v0.z = fmaxf(v0.z * g0.z, 0.0f);
        v0.w = fmaxf(v0.w * g0.w, 0.0f);
        __stcs(&ob0[it * 512 + t], v0);             // streaming store
    }
    ((float4*)red)[t] = vmax;
    __syncthreads();
    if (t < 64) {
        float mv = -INFINITY;
#pragma unroll 8
        for (int i = 0; i < 32; ++i) mv = fmaxf(mv, red[t + 64 * i]);
        msh[t] = mv;
    }
    __syncthreads();

    // ---- step 4: gate for b1 -------------------------------------------------
    compute_gate(b1, t, msh, c0, c1, up, hsh, gate, ws);
    float4 g1 = make_float4(gate[p0], gate[p0 + 1], gate[p0 + 2], gate[p0 + 3]);

    // ---- step 5: out[b1] = relu(x[b1]*g1)  (L2 read + DRAM write) -----------
#pragma unroll 8
    for (int it = 0; it < 32; ++it) {
        float4 v = __ldcs(&xb1[it * 512 + t]);
        v.x = fmaxf(v.x * g1.x, 0.0f);
        v.y = fmaxf(v.y * g1.y, 0.0f);
        v.z = fmaxf(v.z * g1.z, 0.0f);
        v.w = fmaxf(v.w * g1.w, 0.0f);
        __stcs(&ob1[it * 512 + t], v);
    }
}

extern "C" void kernel_launch(void* const* d_in, const int* in_sizes, int n_in,
                              void* d_out, int out_size) {
    const float* x  = (const float*)d_in[0];
    const float* w1 = (const float*)d_in[1];
    const float* w5 = (const float*)d_in[2];
    const float* b5 = (const float*)d_in[3];
    const float* w6 = (const float*)d_in[4];
    const float* b6 = (const float*)d_in[5];
    float* out = (float*)d_out;

    sa_layer_kernel<<<256, 512>>>(x, w1, w5, b5, w6, b6, out);
}

// round 10
// speedup vs baseline: 1.3362x; 1.3362x over previous
#include <cuda_runtime.h>
#include <stdint.h>
#include <math.h>

// ---------------------------------------------------------------------------
// JAX threefry2x32 (key = (0,1) from jax.random.key(1)), partitionable mode:
// bits[j] = out0 ^ out1 of threefry2x32((0,1), (hi=0, lo=j))
// (verified exact: rel_err 5.3e-8)
// ---------------------------------------------------------------------------
__device__ __forceinline__ uint32_t rotl32(uint32_t x, int r) {
    return (x << r) | (x >> (32 - r));
}

__device__ __forceinline__ uint32_t jax_bits(uint32_t j) {
    uint32_t x0 = 0u, x1 = j;
    const uint32_t ks0 = 0u, ks1 = 1u, ks2 = 0x1BD11BDBu;
    x0 += ks0; x1 += ks1;
#define TF_R(r) { x0 += x1; x1 = rotl32(x1, (r)); x1 ^= x0; }
    TF_R(13) TF_R(15) TF_R(26) TF_R(6)
    x0 += ks1; x1 += ks2 + 1u;
    TF_R(17) TF_R(29) TF_R(16) TF_R(24)
    x0 += ks2; x1 += ks0 + 2u;
    TF_R(13) TF_R(15) TF_R(26) TF_R(6)
    x0 += ks0; x1 += ks1 + 3u;
    TF_R(17) TF_R(29) TF_R(16) TF_R(24)
    x0 += ks1; x1 += ks2 + 4u;
    TF_R(13) TF_R(15) TF_R(26) TF_R(6)
    x0 += ks2; x1 += ks0 + 5u;
#undef TF_R
    return x0 ^ x1;
}

__device__ __forceinline__ float jax_gumbel(uint32_t j) {
    uint32_t bits = jax_bits(j);
    float f = __uint_as_float((bits >> 9) | 0x3f800000u) - 1.0f;
    const float TINY = 1.1754943508222875e-38f;
    float u = fmaxf(TINY, f + TINY);
    return -logf(-logf(u));
}

__device__ __forceinline__ void lin_coef(int v, int& a, int& b, float& wa, float& wb) {
    int j = v >> 1;
    if ((v & 1) == 0) { a = j - 1; b = j;     wa = 0.25f; wb = 0.75f; }
    else              { a = j;     b = j + 1; wa = 0.75f; wb = 0.25f; }
    a = max(0, min(3, a));
    b = max(0, min(3, b));
}

__device__ __forceinline__ float4 fmax4(float4 a, float4 b) {
    a.x = fmaxf(a.x, b.x); a.y = fmaxf(a.y, b.y);
    a.z = fmaxf(a.z, b.z); a.w = fmaxf(a.w, b.w);
    return a;
}

// ---------------------------------------------------------------------------
// One block per batch, 512 threads. Deep-MLP streaming passes (8 LDG.128 in
// flight per thread) to escape the Little's-law equilibrium seen in R4/R8.
// ---------------------------------------------------------------------------
__global__ void __launch_bounds__(512, 2)
sa_layer_kernel(const float* __restrict__ x,
                const float* __restrict__ w1,
                const float* __restrict__ w5,
                const float* __restrict__ b5,
                const float* __restrict__ w6,
                const float* __restrict__ b6,
                float* __restrict__ out)
{
    __shared__ float red[2048];
    __shared__ float msh[64];
    __shared__ float c0[16], c1[16], up[64];
    __shared__ float hsh[256];
    __shared__ float gate[64];
    __shared__ float ws[122];

    const int t = threadIdx.x;
    const int b = blockIdx.x;
    const float4* xb = (const float4*)(x + (size_t)b * 65536);
    float4* ob = (float4*)(out + (size_t)b * 65536);

    if (t < 9)        ws[t] = w1[t];
    else if (t < 81)  ws[t] = w5[t - 9];
    else if (t < 85)  ws[t] = b5[t - 81];
    else if (t < 121) ws[t] = w6[t - 85];
    else if (t == 121) ws[121] = b6[0];

    // ---- Phase 1: channel max, MLP=8 ----------------------------------------
    float4 acc0 = make_float4(-INFINITY, -INFINITY, -INFINITY, -INFINITY);
    float4 acc1 = acc0;
    for (int it = 0; it < 4; ++it) {
        float4 r[8];
#pragma unroll
        for (int k = 0; k < 8; ++k)
            r[k] = __ldg(&xb[(it * 8 + k) * 512 + t]);
#pragma unroll
        for (int k = 0; k < 8; k += 2) {
            acc0 = fmax4(acc0, r[k]);
            acc1 = fmax4(acc1, r[k + 1]);
        }
    }
    ((float4*)red)[t] = fmax4(acc0, acc1);
    __syncthreads();
    if (t < 64) {
        float mv = -INFINITY;
#pragma unroll 8
        for (int i = 0; i < 32; ++i) mv = fmaxf(mv, red[t + 64 * i]);
        msh[t] = mv;
    }
    __syncthreads();

    // ---- Phase 2a: 2x2 windows + probabilistic pool --------------------------
    if (t < 16) {
        int wy = t >> 2, wx = t & 3;
        float win0 = msh[(2 * wy) * 8 + 2 * wx];
        float win1 = msh[(2 * wy) * 8 + 2 * wx + 1];
        float win2 = msh[(2 * wy + 1) * 8 + 2 * wx];
        float win3 = msh[(2 * wy + 1) * 8 + 2 * wx + 1];
        float winv[4] = {win0, win1, win2, win3};
        float winc[4];
#pragma unroll
        for (int k = 0; k < 4; ++k) {
            float v = winv[k];
            winc[k] = (isnan(v) || isinf(v) || v < 0.0f) ? 1e-8f : v;
        }
        uint32_t base = (uint32_t)(b * 64 + t * 4);
        float best = -INFINITY; int arg = 0;
#pragma unroll
        for (int k = 0; k < 4; ++k) {
            float val = winc[k] + jax_gumbel(base + (uint32_t)k);
            if (val > best) { best = val; arg = k; }
        }
        float mo2 = winc[arg];
        float mo3 = fmaxf(fmaxf(win0, win1), fmaxf(win2, win3));
        float ao4 = (win0 + win1 + win2 + win3) * 0.25f;
        c0[t] = 0.1f * mo2 + 0.6f * mo3 + 0.3f * ao4;
    }
    __syncthreads();

    // ---- Phase 2b: 3x3 conv (bias-free) on 4x4 -------------------------------
    if (t < 16) {
        int y = t >> 2, xx = t & 3;
        float acc = 0.0f;
#pragma unroll
        for (int dy = 0; dy < 3; ++dy)
#pragma unroll
            for (int dx = 0; dx < 3; ++dx) {
                int yy = y + dy - 1, xc = xx + dx - 1;
                if (yy >= 0 && yy < 4 && xc >= 0 && xc < 4)
                    acc += c0[yy * 4 + xc] * ws[dy * 3 + dx];
            }
        c1[t] = acc;
    }
    __syncthreads();

    // ---- Phase 2c: bilinear upsample 4->8 ------------------------------------
    if (t < 64) {
        int y = t >> 3, xx = t & 7;
        int ya, yb2, xa, xb2; float wya, wyb, wxa, wxb;
        lin_coef(y, ya, yb2, wya, wyb);
        lin_coef(xx, xa, xb2, wxa, wxb);
        up[t] = wya * (wxa * c1[ya * 4 + xa] + wxb * c1[ya * 4 + xb2]) +
                wyb * (wxa * c1[yb2 * 4 + xa] + wxb * c1[yb2 * 4 + xb2]);
    }
    __syncthreads();

    // ---- Phase 2d: conv5 (2->4 ch, 3x3) + relu -------------------------------
    if (t < 256) {
        int o = t >> 6, p = t & 63, y = p >> 3, xx = p & 7;
        float acc = ws[81 + o];
#pragma unroll
        for (int dy = 0; dy < 3; ++dy)
#pragma unroll
            for (int dx = 0; dx < 3; ++dx) {
                int yy = y + dy - 1, xc = xx + dx - 1;
                if (yy >= 0 && yy < 8 && xc >= 0 && xc < 8) {
                    int pp = yy * 8 + xc;
                    acc += msh[pp] * ws[9 + ((o * 2 + 0) * 3 + dy) * 3 + dx];
                    acc += up[pp]  * ws[9 + ((o * 2 + 1) * 3 + dy) * 3 + dx];
                }
            }
        hsh[o * 64 + p] = fmaxf(acc, 0.0f);
    }
    __syncthreads();

    // ---- Phase 2e: conv6 (4->1 ch, 3x3) + sigmoid ----------------------------
    if (t < 64) {
        int y = t >> 3, xx = t & 7;
        float acc = ws[121];
#pragma unroll
        for (int o = 0; o < 4; ++o)
#pragma unroll
            for (int dy = 0; dy < 3; ++dy)
#pragma unroll
                for (int dx = 0; dx < 3; ++dx) {
                    int yy = y + dy - 1, xc = xx + dx - 1;
                    if (yy >= 0 && yy < 8 && xc >= 0 && xc < 8)
                        acc += hsh[o * 64 + yy * 8 + xc] * ws[85 + (o * 3 + dy) * 3 + dx];
                }
        gate[t] = 1.0f / (1.0f + expf(-acc));
    }
    __syncthreads();

    // ---- Phase 3: out = relu(x * gate), MLP=8 (reads are L2 hits) -----------
    const int p0 = (t & 15) * 4;
    const float4 g4 = make_float4(gate[p0], gate[p0 + 1], gate[p0 + 2], gate[p0 + 3]);
    for (int it = 0; it < 4; ++it) {
        float4 r[8];
#pragma unroll
        for (int k = 0; k < 8; ++k)
            r[k] = __ldcs(&xb[(it * 8 + k) * 512 + t]);   // L2 hit, evict-first
#pragma unroll
        for (int k = 0; k < 8; ++k) {
            r[k].x = fmaxf(r[k].x * g4.x, 0.0f);
            r[k].y = fmaxf(r[k].y * g4.y, 0.0f);
            r[k].z = fmaxf(r[k].z * g4.z, 0.0f);
            r[k].w = fmaxf(r[k].w * g4.w, 0.0f);
            __stcs(&ob[(it * 8 + k) * 512 + t], r[k]);    // streaming store
        }
    }
}

extern "C" void kernel_launch(void* const* d_in, const int* in_sizes, int n_in,
                              void* d_out, int out_size) {
    const float* x  = (const float*)d_in[0];
    const float* w1 = (const float*)d_in[1];
    const float* w5 = (const float*)d_in[2];
    const float* b5 = (const float*)d_in[3];
    const float* w6 = (const float*)d_in[4];
    const float* b6 = (const float*)d_in[5];
    float* out = (float*)d_out;

    sa_layer_kernel<<<512, 512>>>(x, w1, w5, b5, w6, b6, out);
}